// round 2
// baseline (speedup 1.0000x reference)
#include <cuda_runtime.h>
#include <cstdint>

// Problem constants
#define BB      512
#define TT      256
#define D_IN    64
#define D_STATE 64
#define NN      2048
#define D_OUT   10
#define KAUG    128

// 16 neuron-groups x 8 batch-groups = 128 persistent CTAs (1/SM)
#define NG      16
#define BG      8
#define NT      128      // neurons per CTA
#define BT      64       // batch rows per CTA
#define NCTAS   (NG * BG)
#define THREADS 512

// SMEM layout (floats), strides padded to 132 (33 banks) => conflict-free
#define ENC_STRIDE 132
#define SDT_STRIDE 132
#define X_OFF    0
#define ENC_OFF  (X_OFF + BT * KAUG)                 // 8192
#define SDT_OFF  (ENC_OFF + NT * ENC_STRIDE)         // +16896
#define A_OFF    (SDT_OFF + D_STATE * SDT_STRIDE)    // +8448
#define DEC_OFF  (A_OFF + BT * NT)                   // +8192
#define SMEM_FLOATS (DEC_OFF + NT * D_OUT)
#define SMEM_BYTES  (SMEM_FLOATS * 4)

// Global scratch (static __device__ — no allocation)
__device__ float g_partials[NG][BB][D_STATE];  // per-neuron-group partial s
__device__ float g_ssum[BB * D_STATE];         // reduced state (single buffer)
__device__ float g_ypart[NG][BB][D_OUT];       // per-group partial outputs

// Self-cleaning grid barrier (gen monotonic across graph replays)
__device__ unsigned g_count = 0;
__device__ volatile unsigned g_gen = 0;

__device__ __forceinline__ void gsync() {
    __syncthreads();
    if (threadIdx.x == 0) {
        __threadfence();
        unsigned gen = g_gen;  // read BEFORE arriving
        unsigned prev = atomicAdd(&g_count, 1);
        if (prev == NCTAS - 1) {
            g_count = 0;
            __threadfence();
            g_gen = gen + 1;
        } else {
            while (g_gen == gen) { }
            __threadfence();
        }
    }
    __syncthreads();
}

// Packed f32x2 FMA (Blackwell): lanewise d = a*b + c on two f32
__device__ __forceinline__ unsigned long long fma2(unsigned long long a,
                                                   unsigned long long b,
                                                   unsigned long long c) {
    unsigned long long d;
    asm("fma.rn.f32x2 %0, %1, %2, %3;" : "=l"(d) : "l"(a), "l"(b), "l"(c));
    return d;
}

__device__ __forceinline__ float lanesum(unsigned long long v) {
    return __uint_as_float((unsigned)v) + __uint_as_float((unsigned)(v >> 32));
}

__global__ void __launch_bounds__(THREADS, 1)
nef_kernel(const float* __restrict__ seq,     // [B][T][D_IN]
           const float* __restrict__ enc,     // [NN][KAUG]
           const float* __restrict__ bias,    // [NN]
           const float* __restrict__ gain,    // [NN]
           const float* __restrict__ sdec,    // [NN][D_STATE]
           const float* __restrict__ dec,     // [NN][D_OUT]
           float* __restrict__ out)           // [B][D_OUT]
{
    extern __shared__ float smem[];
    float* x_s   = smem + X_OFF;
    float* enc_s = smem + ENC_OFF;
    float* sdt_s = smem + SDT_OFF;
    float* a_s   = smem + A_OFF;
    float* dec_s = smem + DEC_OFF;

    const int tid   = threadIdx.x;
    const int ni    = blockIdx.x & (NG - 1);
    const int bi    = blockIdx.x >> 4;
    const int nbase = ni * NT;
    const int bbase = bi * BT;
    const int tn    = tid & 31;          // lane
    const int tw    = tid >> 5;          // warp 0..15
    const int twb   = tw & 7;            // batch octet: rows twb*8 + i
    const int jh    = tw >> 3;           // 0/1: n-half (GEMM1) / d-half (GEMM2)

    // ---- one-time weight staging into SMEM ----
    for (int idx = tid * 4; idx < NT * KAUG; idx += THREADS * 4) {
        int n = idx >> 7, k = idx & 127;
        float4 v = *(const float4*)&enc[(nbase + n) * KAUG + k];
        *(float4*)&enc_s[n * ENC_STRIDE + k] = v;
    }
    for (int idx = tid; idx < NT * D_STATE; idx += THREADS) {
        int n = idx >> 6, d = idx & 63;
        sdt_s[d * SDT_STRIDE + n] = sdec[(nbase + n) * D_STATE + d];
    }
    for (int idx = tid; idx < NT * D_OUT; idx += THREADS)
        dec_s[idx] = dec[nbase * D_OUT + idx];

    float gj[2], bj[2];
#pragma unroll
    for (int j = 0; j < 2; j++) {
        gj[j] = gain[nbase + tn + 32 * j + 64 * jh];
        bj[j] = bias[nbase + tn + 32 * j + 64 * jh];
    }

    // ---- prologue: x_s = [u(0) | 0]  (no grid sync needed; s0 = 0) ----
    for (int idx = tid * 4; idx < BT * KAUG; idx += THREADS * 4) {
        int b = idx >> 7, k = idx & 127;
        float4 v;
        if (k < D_IN)
            v = *(const float4*)&seq[((size_t)(bbase + b) * TT) * D_IN + k];
        else
            v = make_float4(0.f, 0.f, 0.f, 0.f);
        *(float4*)&x_s[b * KAUG + k] = v;
    }
    __syncthreads();

    for (int t = 0; t < TT; t++) {
        // ---- GEMM1: a[b][n] = |gain*(x.e) + bias|  (f32x2 over k) ----
        {
            unsigned long long acc[8][2];
#pragma unroll
            for (int i = 0; i < 8; i++) { acc[i][0] = 0ULL; acc[i][1] = 0ULL; }

            const float* xb = x_s + (twb * 8) * KAUG;
            const float* e0 = enc_s + (tn + 64 * jh) * ENC_STRIDE;

#pragma unroll 2
            for (int kk = 0; kk < KAUG; kk += 4) {
                ulonglong2 ev0 = *(const ulonglong2*)(e0 + kk);
                ulonglong2 ev1 = *(const ulonglong2*)(e0 + 32 * ENC_STRIDE + kk);
#pragma unroll
                for (int i = 0; i < 8; i++) {
                    ulonglong2 xv = *(const ulonglong2*)(xb + i * KAUG + kk);
                    acc[i][0] = fma2(xv.x, ev0.x, acc[i][0]);
                    acc[i][0] = fma2(xv.y, ev0.y, acc[i][0]);
                    acc[i][1] = fma2(xv.x, ev1.x, acc[i][1]);
                    acc[i][1] = fma2(xv.y, ev1.y, acc[i][1]);
                }
            }
#pragma unroll
            for (int i = 0; i < 8; i++)
#pragma unroll
                for (int j = 0; j < 2; j++) {
                    float v = lanesum(acc[i][j]);
                    v = fabsf(fmaf(gj[j], v, bj[j]));
                    a_s[(twb * 8 + i) * NT + tn + 32 * j + 64 * jh] = v;
                }
        }
        __syncthreads();

        if (t == TT - 1) break;   // last step: only activations are needed

        // ---- GEMM2: s_partial[b][d] = a[b][:] . SD[:, d]  (f32x2 over n) ----
        {
            unsigned long long sacc[8];
#pragma unroll
            for (int i = 0; i < 8; i++) sacc[i] = 0ULL;

            const float* ab = a_s + (twb * 8) * NT;
            const float* s0 = sdt_s + (tn + 32 * jh) * SDT_STRIDE;

#pragma unroll 2
            for (int nn0 = 0; nn0 < NT; nn0 += 4) {
                ulonglong2 sv = *(const ulonglong2*)(s0 + nn0);
#pragma unroll
                for (int i = 0; i < 8; i++) {
                    ulonglong2 av = *(const ulonglong2*)(ab + i * NT + nn0);
                    sacc[i] = fma2(av.x, sv.x, sacc[i]);
                    sacc[i] = fma2(av.y, sv.y, sacc[i]);
                }
            }
#pragma unroll
            for (int i = 0; i < 8; i++)
                g_partials[ni][bbase + twb * 8 + i][tn + 32 * jh] = lanesum(sacc[i]);
        }

        // ---- prefetch u(t+1) into x_s (off the critical path) ----
        for (int idx = tid * 4; idx < BT * D_IN; idx += THREADS * 4) {
            int b = idx >> 6, k = idx & 63;
            float4 v = *(const float4*)&seq[((size_t)(bbase + b) * TT + t + 1) * D_IN + k];
            *(float4*)&x_s[b * KAUG + k] = v;
        }

        gsync();   // all partials visible

        // ---- reduce: 16 partials -> g_ssum (vectorized, 64 threads/CTA) ----
        if (tid < 64) {
            int v4 = blockIdx.x * 64 + tid;  // float4 index, 8192 total
            const float4* p = (const float4*)&g_partials[0][0][0];
            float4 s = make_float4(0.f, 0.f, 0.f, 0.f);
#pragma unroll
            for (int g = 0; g < NG; g++) {
                float4 v = p[g * (BB * D_STATE / 4) + v4];
                s.x += v.x; s.y += v.y; s.z += v.z; s.w += v.w;
            }
            *(float4*)&g_ssum[v4 * 4] = s;
        }

        gsync();   // reduced state visible

        // ---- fill s-columns of x_s ----
        {
            int b = tid >> 6, d = tid & 63;   // 512 threads = 64x8 -> strided
            for (int bb2 = b; bb2 < BT; bb2 += 8)
                x_s[bb2 * KAUG + D_IN + d] = g_ssum[(bbase + bb2) * D_STATE + d];
        }
        __syncthreads();
    }

    // ---- partial decode of final activations ----
    for (int idx = tid; idx < BT * D_OUT; idx += THREADS) {
        int b = idx / D_OUT, o = idx - b * D_OUT;
        float acc0 = 0.f, acc1 = 0.f;
#pragma unroll 4
        for (int n = 0; n < NT; n += 2) {
            acc0 += a_s[b * NT + n]     * dec_s[n * D_OUT + o];
            acc1 += a_s[b * NT + n + 1] * dec_s[(n + 1) * D_OUT + o];
        }
        g_ypart[ni][bbase + b][o] = acc0 + acc1;
    }

    gsync();

    // ---- final output reduction (neuron-group 0 CTAs) ----
    if (ni == 0) {
        for (int idx = tid; idx < BT * D_OUT; idx += THREADS) {
            int b = idx / D_OUT, o = idx - b * D_OUT;
            float s = 0.f;
#pragma unroll
            for (int g = 0; g < NG; g++)
                s += g_ypart[g][bbase + b][o];
            out[(bbase + b) * D_OUT + o] = s;
        }
    }
}

extern "C" void kernel_launch(void* const* d_in, const int* in_sizes, int n_in,
                              void* d_out, int out_size) {
    (void)in_sizes; (void)n_in; (void)out_size;
    cudaFuncSetAttribute(nef_kernel, cudaFuncAttributeMaxDynamicSharedMemorySize,
                         SMEM_BYTES);
    nef_kernel<<<NCTAS, THREADS, SMEM_BYTES>>>(
        (const float*)d_in[0],   // seq
        (const float*)d_in[1],   // encoders
        (const float*)d_in[2],   // bias
        (const float*)d_in[3],   // gain
        (const float*)d_in[4],   // state_decoders
        (const float*)d_in[5],   // decoders
        (float*)d_out);
}

// round 4
// speedup vs baseline: 2.0147x; 2.0147x over previous
#include <cuda_runtime.h>
#include <cuda_bf16.h>
#include <cstdint>

// -------- problem constants --------
#define BB      512
#define TT      256
#define D_IN    64
#define D_STATE 64
#define NN      2048
#define D_OUT   10
#define KAUG    128

// -------- decomposition: 16 neuron-groups x 8 batch-groups = 128 CTAs --------
#define NG      16
#define BG      8
#define NT      128     // neurons per CTA (GEMM1 N, GEMM2 K)
#define BT      64      // batch rows per CTA (M)
#define NCTAS   128
#define THREADS 256

// -------- SMEM: bf16 row-major, stride 136 (68 words ≡ 4 mod 32 -> CF) ----
#define KS      136
#define KSW     68
#define XA_HI   0
#define XA_LO   (XA_HI  + BT * KS)
#define E_HI    (XA_LO  + BT * KS)
#define E_LO    (E_HI   + NT * KS)
#define SDT_HI  (E_LO   + NT * KS)
#define SDT_LO  (SDT_HI + D_STATE * KS)
#define A2_HI   (SDT_LO + D_STATE * KS)
#define A2_LO   (A2_HI  + BT * KS)
#define SMEM_ELEMS (A2_LO + BT * KS)
#define SMEM_BYTES (SMEM_ELEMS * 2)

// -------- global scratch (static; no allocation) --------
__device__ float g_partials[NG][BB][D_STATE];
__device__ float g_ssum[BB * D_STATE];
__device__ float g_ypart[NG][BB][D_OUT];

__device__ unsigned g_count = 0;
__device__ volatile unsigned g_gen = 0;

__device__ __forceinline__ void gsync() {
    __syncthreads();
    if (threadIdx.x == 0) {
        __threadfence();
        unsigned gen = g_gen;                  // read BEFORE arriving
        unsigned prev = atomicAdd(&g_count, 1);
        if (prev == NCTAS - 1) {
            g_count = 0;
            __threadfence();
            g_gen = gen + 1;
        } else {
            while (g_gen == gen) { }
            __threadfence();
        }
    }
    __syncthreads();
}

// -------- warp-level bf16 MMA (sm_80+ baseline PTX; no arch-a gating) -----
__device__ __forceinline__ void mma_bf16(float* c, uint32_t a0, uint32_t a1,
                                         uint32_t a2, uint32_t a3,
                                         uint32_t b0, uint32_t b1) {
    asm volatile(
        "mma.sync.aligned.m16n8k16.row.col.f32.bf16.bf16.f32 "
        "{%0,%1,%2,%3}, {%4,%5,%6,%7}, {%8,%9}, {%0,%1,%2,%3};"
        : "+f"(c[0]), "+f"(c[1]), "+f"(c[2]), "+f"(c[3])
        : "r"(a0), "r"(a1), "r"(a2), "r"(a3), "r"(b0), "r"(b1));
}

// 3-pass split GEMM: C[32x32 warp tile] += A*B^T with A=[rows][K], B=[cols][K]
// passes: (Ah,Bh) + (Al,Bh) + (Ah,Bl)
__device__ __forceinline__ void gemm3(const uint32_t* __restrict__ Ah,
                                      const uint32_t* __restrict__ Al,
                                      const uint32_t* __restrict__ Bh,
                                      const uint32_t* __restrict__ Bl,
                                      int m0, int n0, int g, int t,
                                      float acc[2][4][4]) {
#pragma unroll
    for (int pass = 0; pass < 3; pass++) {
        const uint32_t* A = (pass == 1) ? Al : Ah;
        const uint32_t* B = (pass == 2) ? Bl : Bh;
#pragma unroll
        for (int ks = 0; ks < 8; ks++) {
            const int kw = ks * 8 + t;   // word index: k0/2 + t
            uint32_t a[2][4];
#pragma unroll
            for (int ms = 0; ms < 2; ms++) {
                const int r = m0 + 16 * ms + g;
                a[ms][0] = A[r * KSW + kw];
                a[ms][1] = A[(r + 8) * KSW + kw];
                a[ms][2] = A[r * KSW + kw + 4];
                a[ms][3] = A[(r + 8) * KSW + kw + 4];
            }
#pragma unroll
            for (int ns = 0; ns < 4; ns++) {
                const int c = n0 + 8 * ns + g;
                uint32_t b0 = B[c * KSW + kw];
                uint32_t b1 = B[c * KSW + kw + 4];
                mma_bf16(acc[0][ns], a[0][0], a[0][1], a[0][2], a[0][3], b0, b1);
                mma_bf16(acc[1][ns], a[1][0], a[1][1], a[1][2], a[1][3], b0, b1);
            }
        }
    }
}

// split two floats into bf16 hi/lo pairs and store packed (k-pair granularity)
__device__ __forceinline__ void split_pair_store(__nv_bfloat16* bh, __nv_bfloat16* bl,
                                                 int row, int kpair, float x, float y) {
    __nv_bfloat162 h, l;
    h.x = __float2bfloat16(x);
    h.y = __float2bfloat16(y);
    l.x = __float2bfloat16(x - __bfloat162float(h.x));
    l.y = __float2bfloat16(y - __bfloat162float(h.y));
    *(__nv_bfloat162*)(bh + row * KS + kpair * 2) = h;
    *(__nv_bfloat162*)(bl + row * KS + kpair * 2) = l;
}

__global__ void __launch_bounds__(THREADS, 1)
nef_kernel(const float* __restrict__ seq,     // [B][T][D_IN]
           const float* __restrict__ enc,     // [NN][KAUG]
           const float* __restrict__ bias,    // [NN]
           const float* __restrict__ gain,    // [NN]
           const float* __restrict__ sdec,    // [NN][D_STATE]
           const float* __restrict__ dec,     // [NN][D_OUT]
           float* __restrict__ out)           // [B][D_OUT]
{
    extern __shared__ __nv_bfloat16 smem[];
    __nv_bfloat16* XAh = smem + XA_HI;
    __nv_bfloat16* XAl = smem + XA_LO;
    __nv_bfloat16* Eh  = smem + E_HI;
    __nv_bfloat16* El  = smem + E_LO;
    __nv_bfloat16* SDh = smem + SDT_HI;
    __nv_bfloat16* SDl = smem + SDT_LO;
    __nv_bfloat16* A2h = smem + A2_HI;
    __nv_bfloat16* A2l = smem + A2_LO;

    const uint32_t* XAh32 = (const uint32_t*)XAh;
    const uint32_t* XAl32 = (const uint32_t*)XAl;
    const uint32_t* Eh32  = (const uint32_t*)Eh;
    const uint32_t* El32  = (const uint32_t*)El;
    const uint32_t* SDh32 = (const uint32_t*)SDh;
    const uint32_t* SDl32 = (const uint32_t*)SDl;
    const uint32_t* A2h32 = (const uint32_t*)A2h;
    const uint32_t* A2l32 = (const uint32_t*)A2l;

    const int tid  = threadIdx.x;
    const int wid  = tid >> 5;
    const int lane = tid & 31;
    const int g    = lane >> 2;          // groupID
    const int t4   = lane & 3;           // thread-in-group
    const int ni   = blockIdx.x & (NG - 1);
    const int bi   = blockIdx.x >> 4;
    const int nbase = ni * NT;
    const int bbase = bi * BT;

    // GEMM1 warp tile: m0a in {0,32}, n0a in {0,32,64,96}
    const int m0a = 32 * (wid & 1);
    const int n0a = 32 * (wid >> 1);

    // ---- one-time weight staging (bf16 hi/lo) ----
    // E: [NT=128 n][K=128], pairs along k
    for (int i = tid; i < NT * (KAUG / 2); i += THREADS) {
        int n = i >> 6, p = i & 63;
        float2 v = *(const float2*)&enc[(nbase + n) * KAUG + 2 * p];
        split_pair_store(Eh, El, n, p, v.x, v.y);
    }
    // SDT: [d][n] = sdec[n][d], pairs along n
    for (int i = tid; i < D_STATE * (NT / 2); i += THREADS) {
        int d = i >> 6, p = i & 63;
        float x = sdec[(nbase + 2 * p) * D_STATE + d];
        float y = sdec[(nbase + 2 * p + 1) * D_STATE + d];
        split_pair_store(SDh, SDl, d, p, x, y);
    }
    // per-thread gain/bias for epilogue1 (columns n0a + 8ns + 2t4 (+1))
    float gj[4][2], bj[4][2];
#pragma unroll
    for (int ns = 0; ns < 4; ns++) {
        int n = nbase + n0a + 8 * ns + 2 * t4;
        gj[ns][0] = gain[n];     gj[ns][1] = gain[n + 1];
        bj[ns][0] = bias[n];     bj[ns][1] = bias[n + 1];
    }

    // ---- initial XA = [u(0) | 0] ----
    for (int i = tid; i < BT * (D_IN / 2); i += THREADS) {
        int r = i >> 5, p = i & 31;
        float2 v = *(const float2*)&seq[((size_t)(bbase + r) * TT) * D_IN + 2 * p];
        split_pair_store(XAh, XAl, r, p, v.x, v.y);
    }
    for (int i = tid; i < BT * (D_STATE / 2); i += THREADS) {
        int r = i >> 5, p = i & 31;
        split_pair_store(XAh, XAl, r, 32 + p, 0.f, 0.f);
    }
    __syncthreads();

    for (int t = 0; t < TT; t++) {
        // ======== GEMM1: a = XA @ E^T  (all 8 warps, 32x32 tiles) ========
        float acc[2][4][4];
#pragma unroll
        for (int ms = 0; ms < 2; ms++)
#pragma unroll
            for (int ns = 0; ns < 4; ns++)
#pragma unroll
                for (int q = 0; q < 4; q++) acc[ms][ns][q] = 0.f;

        gemm3(XAh32, XAl32, Eh32, El32, m0a, n0a, g, t4, acc);

        // ======== epilogue 1: act = |gain*v + bias| -> A2 hi/lo ========
#pragma unroll
        for (int ms = 0; ms < 2; ms++)
#pragma unroll
            for (int ns = 0; ns < 4; ns++) {
                float v0 = fabsf(fmaf(gj[ns][0], acc[ms][ns][0], bj[ns][0]));
                float v1 = fabsf(fmaf(gj[ns][1], acc[ms][ns][1], bj[ns][1]));
                float v2 = fabsf(fmaf(gj[ns][0], acc[ms][ns][2], bj[ns][0]));
                float v3 = fabsf(fmaf(gj[ns][1], acc[ms][ns][3], bj[ns][1]));
                int r0 = m0a + 16 * ms + g;
                int kp = (n0a + 8 * ns + 2 * t4) >> 1;
                split_pair_store(A2h, A2l, r0,     kp, v0, v1);
                split_pair_store(A2h, A2l, r0 + 8, kp, v2, v3);
            }

        if (t == TT - 1) break;

        __syncthreads();   // A2 visible to GEMM2 warps

        if (wid < 4) {
            // ======== GEMM2: s_part = a @ SD  (warps 0-3, 32x32 tiles) ====
            const int m0b = 32 * (wid & 1);
            const int d0b = 32 * (wid >> 1);
            float acc2[2][4][4];
#pragma unroll
            for (int ms = 0; ms < 2; ms++)
#pragma unroll
                for (int ns = 0; ns < 4; ns++)
#pragma unroll
                    for (int q = 0; q < 4; q++) acc2[ms][ns][q] = 0.f;

            gemm3(A2h32, A2l32, SDh32, SDl32, m0b, d0b, g, t4, acc2);

            // epilogue 2: write state partials
#pragma unroll
            for (int ms = 0; ms < 2; ms++)
#pragma unroll
                for (int ns = 0; ns < 4; ns++) {
                    int r0 = m0b + 16 * ms + g;
                    int d  = d0b + 8 * ns + 2 * t4;
                    float2 p0 = make_float2(acc2[ms][ns][0], acc2[ms][ns][1]);
                    float2 p1 = make_float2(acc2[ms][ns][2], acc2[ms][ns][3]);
                    *(float2*)&g_partials[ni][bbase + r0][d]     = p0;
                    *(float2*)&g_partials[ni][bbase + r0 + 8][d] = p1;
                }
        } else {
            // ---- concurrent prefetch: u(t+1) -> XA u-part (XA dead) ----
            for (int i = tid - 128; i < BT * (D_IN / 2); i += 128) {
                int r = i >> 5, p = i & 31;
                float2 v = *(const float2*)&seq[((size_t)(bbase + r) * TT + t + 1) * D_IN + 2 * p];
                split_pair_store(XAh, XAl, r, p, v.x, v.y);
            }
        }

        gsync();   // all partials globally visible

        // ---- reduce: 16 partials -> g_ssum (64 threads, float4) ----
        if (tid < 64) {
            int q = blockIdx.x * 64 + tid;   // float4 index, 8192 total
            const float4* p4 = (const float4*)&g_partials[0][0][0];
            float4 s = make_float4(0.f, 0.f, 0.f, 0.f);
#pragma unroll
            for (int gg = 0; gg < NG; gg++) {
                float4 v = p4[gg * (BB * D_STATE / 4) + q];
                s.x += v.x; s.y += v.y; s.z += v.z; s.w += v.w;
            }
            *(float4*)&g_ssum[q * 4] = s;
        }

        gsync();   // reduced state visible

        // ---- fill s-part of XA ----
        for (int i = tid; i < BT * (D_STATE / 2); i += THREADS) {
            int r = i >> 5, p = i & 31;
            float2 v = *(const float2*)&g_ssum[(bbase + r) * D_STATE + 2 * p];
            split_pair_store(XAh, XAl, r, 32 + p, v.x, v.y);
        }
        __syncthreads();
    }

    // ======== final decode: y = a @ dec ========
    __syncthreads();
    for (int idx = tid; idx < BT * D_OUT; idx += THREADS) {
        int b = idx / D_OUT, o = idx - b * D_OUT;
        float s = 0.f;
#pragma unroll 4
        for (int n = 0; n < NT; n++) {
            float a = __bfloat162float(A2h[b * KS + n]) + __bfloat162float(A2l[b * KS + n]);
            s += a * dec[(nbase + n) * D_OUT + o];
        }
        g_ypart[ni][bbase + b][o] = s;
    }
    gsync();

    if (ni == 0) {
        for (int idx = tid; idx < BT * D_OUT; idx += THREADS) {
            int b = idx / D_OUT, o = idx - b * D_OUT;
            float s = 0.f;
#pragma unroll
            for (int gg = 0; gg < NG; gg++)
                s += g_ypart[gg][bbase + b][o];
            out[(bbase + b) * D_OUT + o] = s;
        }
    }
}

extern "C" void kernel_launch(void* const* d_in, const int* in_sizes, int n_in,
                              void* d_out, int out_size) {
    (void)in_sizes; (void)n_in; (void)out_size;
    cudaFuncSetAttribute(nef_kernel, cudaFuncAttributeMaxDynamicSharedMemorySize,
                         SMEM_BYTES);
    nef_kernel<<<NCTAS, THREADS, SMEM_BYTES>>>(
        (const float*)d_in[0],   // seq
        (const float*)d_in[1],   // encoders
        (const float*)d_in[2],   // bias
        (const float*)d_in[3],   // gain
        (const float*)d_in[4],   // state_decoders
        (const float*)d_in[5],   // decoders
        (float*)d_out);
}

// round 5
// speedup vs baseline: 2.2103x; 1.0971x over previous
#include <cuda_runtime.h>
#include <cuda_bf16.h>
#include <cstdint>

// -------- problem constants --------
#define BB      512
#define TT      256
#define D_IN    64
#define D_STATE 64
#define NN      2048
#define D_OUT   10
#define KAUG    128

// -------- decomposition: 16 neuron-groups x 8 batch-groups = 128 CTAs --------
#define NG      16
#define BG      8
#define NT      128     // neurons per CTA (GEMM1 N, GEMM2 K)
#define BT      64      // batch rows per CTA (M)
#define NCTAS   128
#define THREADS 512

// -------- SMEM: bf16 row-major, stride 136 (68 words = 4 mod 32 -> CF) ----
#define KS      136
#define KSW     68
#define XA_HI   0
#define XA_LO   (XA_HI  + BT * KS)
#define E_HI    (XA_LO  + BT * KS)
#define E_LO    (E_HI   + NT * KS)
#define SDT_HI  (E_LO   + NT * KS)
#define SDT_LO  (SDT_HI + D_STATE * KS)
#define A2_HI   (SDT_LO + D_STATE * KS)
#define A2_LO   (A2_HI  + BT * KS)
#define SMEM_ELEMS (A2_LO + BT * KS)
#define SMEM_BYTES (SMEM_ELEMS * 2)

// -------- global scratch (static; no allocation) --------
__device__ float g_partials[NG][BB][D_STATE];
__device__ float g_ypart[NG][BB][D_OUT];

__device__ unsigned g_count = 0;
__device__ volatile unsigned g_gen = 0;

__device__ __forceinline__ void gsync() {
    __syncthreads();
    if (threadIdx.x == 0) {
        __threadfence();
        unsigned gen = g_gen;                  // read BEFORE arriving
        unsigned prev = atomicAdd(&g_count, 1);
        if (prev == NCTAS - 1) {
            g_count = 0;
            __threadfence();
            g_gen = gen + 1;
        } else {
            while (g_gen == gen) { }
            __threadfence();
        }
    }
    __syncthreads();
}

// -------- warp-level bf16 MMA (sm_80+ baseline PTX; no arch-a gating) -----
__device__ __forceinline__ void mma_bf16(float* c, uint32_t a0, uint32_t a1,
                                         uint32_t a2, uint32_t a3,
                                         uint32_t b0, uint32_t b1) {
    asm volatile(
        "mma.sync.aligned.m16n8k16.row.col.f32.bf16.bf16.f32 "
        "{%0,%1,%2,%3}, {%4,%5,%6,%7}, {%8,%9}, {%0,%1,%2,%3};"
        : "+f"(c[0]), "+f"(c[1]), "+f"(c[2]), "+f"(c[3])
        : "r"(a0), "r"(a1), "r"(a2), "r"(a3), "r"(b0), "r"(b1));
}

// 3-pass split GEMM, 16x32 warp tile: C += A*B^T, A=[rows][K], B=[cols][K]
// passes: (Ah,Bh) + (Al,Bh) + (Ah,Bl); K = 128 (8 k16 steps)
__device__ __forceinline__ void gemm3(const uint32_t* __restrict__ Ah,
                                      const uint32_t* __restrict__ Al,
                                      const uint32_t* __restrict__ Bh,
                                      const uint32_t* __restrict__ Bl,
                                      int m0, int n0, int g, int t,
                                      float acc[4][4]) {
#pragma unroll
    for (int pass = 0; pass < 3; pass++) {
        const uint32_t* A = (pass == 1) ? Al : Ah;
        const uint32_t* B = (pass == 2) ? Bl : Bh;
#pragma unroll
        for (int ks = 0; ks < 8; ks++) {
            const int kw = ks * 8 + t;            // word index: k0/2 + t
            const int r = m0 + g;
            uint32_t a0 = A[r * KSW + kw];
            uint32_t a1 = A[(r + 8) * KSW + kw];
            uint32_t a2 = A[r * KSW + kw + 4];
            uint32_t a3 = A[(r + 8) * KSW + kw + 4];
#pragma unroll
            for (int ns = 0; ns < 4; ns++) {
                const int c = n0 + 8 * ns + g;
                uint32_t b0 = B[c * KSW + kw];
                uint32_t b1 = B[c * KSW + kw + 4];
                mma_bf16(acc[ns], a0, a1, a2, a3, b0, b1);
            }
        }
    }
}

// split two floats into bf16 hi/lo pairs and store packed (k-pair granularity)
__device__ __forceinline__ void split_pair_store(__nv_bfloat16* bh, __nv_bfloat16* bl,
                                                 int row, int kpair, float x, float y) {
    __nv_bfloat162 h, l;
    h.x = __float2bfloat16(x);
    h.y = __float2bfloat16(y);
    l.x = __float2bfloat16(x - __bfloat162float(h.x));
    l.y = __float2bfloat16(y - __bfloat162float(h.y));
    *(__nv_bfloat162*)(bh + row * KS + kpair * 2) = h;
    *(__nv_bfloat162*)(bl + row * KS + kpair * 2) = l;
}

__global__ void __launch_bounds__(THREADS, 1)
nef_kernel(const float* __restrict__ seq,     // [B][T][D_IN]
           const float* __restrict__ enc,     // [NN][KAUG]
           const float* __restrict__ bias,    // [NN]
           const float* __restrict__ gain,    // [NN]
           const float* __restrict__ sdec,    // [NN][D_STATE]
           const float* __restrict__ dec,     // [NN][D_OUT]
           float* __restrict__ out)           // [B][D_OUT]
{
    extern __shared__ __nv_bfloat16 smem[];
    __nv_bfloat16* XAh = smem + XA_HI;
    __nv_bfloat16* XAl = smem + XA_LO;
    __nv_bfloat16* Eh  = smem + E_HI;
    __nv_bfloat16* El  = smem + E_LO;
    __nv_bfloat16* SDh = smem + SDT_HI;
    __nv_bfloat16* SDl = smem + SDT_LO;
    __nv_bfloat16* A2h = smem + A2_HI;
    __nv_bfloat16* A2l = smem + A2_LO;

    const uint32_t* XAh32 = (const uint32_t*)XAh;
    const uint32_t* XAl32 = (const uint32_t*)XAl;
    const uint32_t* Eh32  = (const uint32_t*)Eh;
    const uint32_t* El32  = (const uint32_t*)El;
    const uint32_t* SDh32 = (const uint32_t*)SDh;
    const uint32_t* SDl32 = (const uint32_t*)SDl;
    const uint32_t* A2h32 = (const uint32_t*)A2h;
    const uint32_t* A2l32 = (const uint32_t*)A2l;

    const int tid  = threadIdx.x;
    const int wid  = tid >> 5;
    const int lane = tid & 31;
    const int g    = lane >> 2;          // groupID
    const int t4   = lane & 3;           // thread-in-group
    const int ni   = blockIdx.x & (NG - 1);
    const int bi   = blockIdx.x >> 4;
    const int nbase = ni * NT;
    const int bbase = bi * BT;

    // GEMM1 warp tile (16x32): m0a in {0,16,32,48}, n0a in {0,32,64,96}
    const int m0a = 16 * (wid & 3);
    const int n0a = 32 * (wid >> 2);

    // ---- one-time weight staging (bf16 hi/lo) ----
    for (int i = tid; i < NT * (KAUG / 2); i += THREADS) {
        int n = i >> 6, p = i & 63;
        float2 v = *(const float2*)&enc[(nbase + n) * KAUG + 2 * p];
        split_pair_store(Eh, El, n, p, v.x, v.y);
    }
    for (int i = tid; i < D_STATE * (NT / 2); i += THREADS) {
        int d = i >> 6, p = i & 63;
        float x = sdec[(nbase + 2 * p) * D_STATE + d];
        float y = sdec[(nbase + 2 * p + 1) * D_STATE + d];
        split_pair_store(SDh, SDl, d, p, x, y);
    }
    // per-thread gain/bias for epilogue1 (columns n0a + 8ns + 2t4 (+1))
    float gj[4][2], bj[4][2];
#pragma unroll
    for (int ns = 0; ns < 4; ns++) {
        int n = nbase + n0a + 8 * ns + 2 * t4;
        gj[ns][0] = gain[n];     gj[ns][1] = gain[n + 1];
        bj[ns][0] = bias[n];     bj[ns][1] = bias[n + 1];
    }

    // ---- initial XA = [u(0) | 0] ----
    for (int i = tid; i < BT * (D_IN / 2); i += THREADS) {
        int r = i >> 5, p = i & 31;
        float2 v = *(const float2*)&seq[((size_t)(bbase + r) * TT) * D_IN + 2 * p];
        split_pair_store(XAh, XAl, r, p, v.x, v.y);
    }
    for (int i = tid; i < BT * (D_STATE / 2); i += THREADS) {
        int r = i >> 5, p = i & 31;
        split_pair_store(XAh, XAl, r, 32 + p, 0.f, 0.f);
    }
    __syncthreads();

    for (int t = 0; t < TT; t++) {
        // ======== GEMM1: a = XA @ E^T (16 warps, 16x32 tiles) ========
        float acc[4][4];
#pragma unroll
        for (int ns = 0; ns < 4; ns++)
#pragma unroll
            for (int q = 0; q < 4; q++) acc[ns][q] = 0.f;

        gemm3(XAh32, XAl32, Eh32, El32, m0a, n0a, g, t4, acc);

        // ======== epilogue 1: act = |gain*v + bias| -> A2 hi/lo ========
#pragma unroll
        for (int ns = 0; ns < 4; ns++) {
            float v0 = fabsf(fmaf(gj[ns][0], acc[ns][0], bj[ns][0]));
            float v1 = fabsf(fmaf(gj[ns][1], acc[ns][1], bj[ns][1]));
            float v2 = fabsf(fmaf(gj[ns][0], acc[ns][2], bj[ns][0]));
            float v3 = fabsf(fmaf(gj[ns][1], acc[ns][3], bj[ns][1]));
            int r0 = m0a + g;
            int kp = (n0a + 8 * ns + 2 * t4) >> 1;
            split_pair_store(A2h, A2l, r0,     kp, v0, v1);
            split_pair_store(A2h, A2l, r0 + 8, kp, v2, v3);
        }

        if (t == TT - 1) break;

        __syncthreads();   // A2 visible to GEMM2 warps

        if (wid < 8) {
            // ======== GEMM2: s_part = a @ SD (warps 0-7, 16x32 tiles) ====
            const int m0b = 16 * (wid & 3);
            const int d0b = 32 * (wid >> 2);
            float acc2[4][4];
#pragma unroll
            for (int ns = 0; ns < 4; ns++)
#pragma unroll
                for (int q = 0; q < 4; q++) acc2[ns][q] = 0.f;

            gemm3(A2h32, A2l32, SDh32, SDl32, m0b, d0b, g, t4, acc2);

#pragma unroll
            for (int ns = 0; ns < 4; ns++) {
                int r0 = m0b + g;
                int d  = d0b + 8 * ns + 2 * t4;
                *(float2*)&g_partials[ni][bbase + r0][d] =
                    make_float2(acc2[ns][0], acc2[ns][1]);
                *(float2*)&g_partials[ni][bbase + r0 + 8][d] =
                    make_float2(acc2[ns][2], acc2[ns][3]);
            }
        } else {
            // ---- concurrent prefetch: u(t+1) -> XA u-part ----
            for (int i = tid - 256; i < BT * (D_IN / 2); i += 256) {
                int r = i >> 5, p = i & 31;
                float2 v = *(const float2*)&seq[((size_t)(bbase + r) * TT + t + 1) * D_IN + 2 * p];
                split_pair_store(XAh, XAl, r, p, v.x, v.y);
            }
        }

        gsync();   // all partials globally visible (one barrier per step)

        // ---- fused reduce+fill: s[r][d] = sum_g partials[g][bbase+r][d]
        //      directly into XA s-columns (each CTA does its own 64 rows) ----
#pragma unroll
        for (int j = 0; j < 2; j++) {
            int item = tid + THREADS * j;        // 0..1023
            int r  = item >> 4;                  // 0..63
            int dq = item & 15;                  // float4 block within d
            float4 s = make_float4(0.f, 0.f, 0.f, 0.f);
#pragma unroll
            for (int gg = 0; gg < NG; gg++) {
                float4 v = *(const float4*)&g_partials[gg][bbase + r][dq * 4];
                s.x += v.x; s.y += v.y; s.z += v.z; s.w += v.w;
            }
            split_pair_store(XAh, XAl, r, 32 + 2 * dq,     s.x, s.y);
            split_pair_store(XAh, XAl, r, 32 + 2 * dq + 1, s.z, s.w);
        }
        __syncthreads();
    }

    // ======== final decode: y = a @ dec ========
    __syncthreads();
    for (int idx = tid; idx < BT * D_OUT; idx += THREADS) {
        int b = idx / D_OUT, o = idx - b * D_OUT;
        float s = 0.f;
#pragma unroll 4
        for (int n = 0; n < NT; n++) {
            float a = __bfloat162float(A2h[b * KS + n]) + __bfloat162float(A2l[b * KS + n]);
            s += a * dec[(nbase + n) * D_OUT + o];
        }
        g_ypart[ni][bbase + b][o] = s;
    }
    gsync();

    if (ni == 0) {
        for (int idx = tid; idx < BT * D_OUT; idx += THREADS) {
            int b = idx / D_OUT, o = idx - b * D_OUT;
            float s = 0.f;
#pragma unroll
            for (int gg = 0; gg < NG; gg++)
                s += g_ypart[gg][bbase + b][o];
            out[(bbase + b) * D_OUT + o] = s;
        }
    }
}

extern "C" void kernel_launch(void* const* d_in, const int* in_sizes, int n_in,
                              void* d_out, int out_size) {
    (void)in_sizes; (void)n_in; (void)out_size;
    cudaFuncSetAttribute(nef_kernel, cudaFuncAttributeMaxDynamicSharedMemorySize,
                         SMEM_BYTES);
    nef_kernel<<<NCTAS, THREADS, SMEM_BYTES>>>(
        (const float*)d_in[0],   // seq
        (const float*)d_in[1],   // encoders
        (const float*)d_in[2],   // bias
        (const float*)d_in[3],   // gain
        (const float*)d_in[4],   // state_decoders
        (const float*)d_in[5],   // decoders
        (float*)d_out);
}